// round 4
// baseline (speedup 1.0000x reference)
#include <cuda_runtime.h>

#define NN 2304          // H*W
#define CC 128           // channels
#define KK 16            // clusters
#define NHEAD 4
#define HCH 32           // head channels
#define C2 256           // 2*C
#define EPSV 1e-6f
#define INV_SCALE 0.17677669529663687f   // 1/sqrt(32)

// -------- scratch (device globals; no allocation allowed) --------
__device__ float g_q[NN * CC];       // scaled by 1/sqrt(HC)
__device__ float g_k[NN * CC];
__device__ float g_v[NN * CC];
__device__ float g_ksort[NN * CC];   // k rows permuted into cluster order
__device__ float g_vsort[NN * CC];
__device__ float g_pcs[NN * NN];     // pc columns permuted into cluster order
__device__ int   g_perm[NN];         // sorted pos -> original index
__device__ int   g_labsort[NN];      // label at sorted pos
__device__ int   g_coff[KK + 1];     // cluster offsets in sorted order
__device__ float g_cent[KK * CC];
__device__ float g_attn[NN * CC];    // attention out, [N][C], C = h*32+d
__device__ float g_h1[NN * C2];
__device__ float g_rs1[NN * CC];     // channel-major [C][N]

// ================= projection: out[n][co] = (sum_ci img[ci][n]*w[ci][co]+b[co])*scale
__global__ __launch_bounds__(256) void proj_kernel(
    const float* __restrict__ img, const float* __restrict__ w,
    const float* __restrict__ b, float* __restrict__ out, float scale) {
    __shared__ float xs[32 * 129];
    int n0 = blockIdx.x * 32;
    int tid = threadIdx.x;
    for (int idx = tid; idx < 32 * 128; idx += 256) {
        int nn = idx & 31, ci = idx >> 5;
        xs[nn * 129 + ci] = img[ci * NN + n0 + nn];
    }
    __syncthreads();
    int co = tid & 127, half = tid >> 7;
    float acc[16];
#pragma unroll
    for (int n = 0; n < 16; n++) acc[n] = 0.f;
    for (int ci = 0; ci < 128; ci++) {
        float wv = w[ci * 128 + co];
#pragma unroll
        for (int n = 0; n < 16; n++) acc[n] += xs[(half * 16 + n) * 129 + ci] * wv;
    }
    float bv = b[co];
#pragma unroll
    for (int n = 0; n < 16; n++)
        out[(n0 + half * 16 + n) * CC + co] = (acc[n] + bv) * scale;
}

// ================= stable counting sort of labels (single block, 256 threads)
#define CHUNK 9   // 256*9 = 2304
__global__ __launch_bounds__(256) void sortidx_kernel(const int* __restrict__ labels) {
    __shared__ int labs[NN];
    __shared__ int cnt[256][KK];
    __shared__ int tot[KK], coff[KK + 1];
    int tid = threadIdx.x;
    for (int i = tid; i < NN; i += 256) labs[i] = labels[i];
#pragma unroll
    for (int k = 0; k < KK; k++) cnt[tid][k] = 0;
    __syncthreads();
    int base = tid * CHUNK;
#pragma unroll
    for (int c = 0; c < CHUNK; c++) cnt[tid][labs[base + c]]++;
    __syncthreads();
    if (tid < KK) {
        int s = 0;
        for (int t = 0; t < 256; t++) s += cnt[t][tid];
        tot[tid] = s;
    }
    __syncthreads();
    if (tid == 0) {
        int s = 0;
        for (int k = 0; k < KK; k++) { coff[k] = s; s += tot[k]; }
        coff[KK] = s;
        for (int k = 0; k <= KK; k++) g_coff[k] = coff[k];
    }
    __syncthreads();
    if (tid < KK) {   // turn cnt[t][k] into absolute start positions
        int run = coff[tid];
        for (int t = 0; t < 256; t++) {
            int c = cnt[t][tid];
            cnt[t][tid] = run;
            run += c;
        }
    }
    __syncthreads();
#pragma unroll
    for (int c = 0; c < CHUNK; c++) {
        int n = base + c;
        int k = labs[n];
        int pos = cnt[tid][k]++;
        g_perm[pos] = n;
        g_labsort[pos] = k;
    }
}

// ================= gather k,v rows into sorted order (warp per row, coalesced)
__global__ __launch_bounds__(256) void gather_kv_kernel() {
    int idx = blockIdx.x * 256 + threadIdx.x;   // NN*32 threads
    int pos = idx >> 5, f = idx & 31;
    int j = g_perm[pos];
    ((float4*)g_ksort)[pos * 32 + f] = ((const float4*)g_k)[j * 32 + f];
    ((float4*)g_vsort)[pos * 32 + f] = ((const float4*)g_v)[j * 32 + f];
}

// ================= permute pc columns into sorted order (block per query row)
__global__ __launch_bounds__(256) void pcsort_kernel(const float* __restrict__ pc) {
    __shared__ float row[NN];
    int i = blockIdx.x, tid = threadIdx.x;
    const float* src = pc + (long)i * NN;
    for (int j = tid; j < NN; j += 256) row[j] = src[j];
    __syncthreads();
    float* dst = g_pcs + (long)i * NN;
    for (int p = tid; p < NN; p += 256) dst[p] = row[g_perm[p]];
}

// ================= cluster centers from sorted k (block per cluster)
__global__ __launch_bounds__(128) void centers_kernel() {
    int k = blockIdx.x, tid = threadIdx.x;
    int s = g_coff[k], e = g_coff[k + 1];
    float sum = 0.f;
    for (int p = s; p < e; p++) sum += g_ksort[p * CC + tid];
    g_cent[k * CC + tid] = sum / ((float)(e - s) + EPSV);
}

// ================= fused clustered attention over sorted keys
// 256 threads = 8 warps; each warp owns 4 query rows; fixed-max softmax.
#define RW 4
#define PAD 36   // 9 float4s/row -> stride 9 (odd) -> conflict-free LDS.128
__global__ __launch_bounds__(256) void attn_kernel(const int* __restrict__ labels) {
    __shared__ float qs[32 * PAD];
    __shared__ float cens[KK * PAD];
    __shared__ float cs[32][KK];
    __shared__ float ks[32 * PAD];    // [j][d]
    __shared__ float vsT[32 * PAD];   // [d][j]
    __shared__ float es[8][RW * 32];  // per-warp exp weights
    __shared__ int labt[32];

    int h = blockIdx.y;
    int i0 = blockIdx.x * 32;
    int tid = threadIdx.x;
    int warp = tid >> 5, lane = tid & 31;

    {   // q tile (32 rows) + centers (16 rows), float4 loads
        int r = tid >> 3, d4 = (tid & 7) * 4;
        *(float4*)&qs[r * PAD + d4] = *(const float4*)&g_q[(i0 + r) * CC + h * HCH + d4];
        if (tid < KK * 8)
            *(float4*)&cens[r * PAD + d4] = *(const float4*)&g_cent[r * CC + h * HCH + d4];
    }
    __syncthreads();
#pragma unroll
    for (int p = 0; p < 2; p++) {   // cs[r][t] = q_r . center_t
        int task = tid + 256 * p;
        int r = task >> 4, t = task & 15;
        float s = 0.f;
#pragma unroll
        for (int d = 0; d < 32; d++) s += qs[r * PAD + d] * cens[t * PAD + d];
        cs[r][t] = s;
    }
    __syncthreads();

    int mylab[RW];
    const float* pcrow[RW];
#pragma unroll
    for (int r = 0; r < RW; r++) {
        int i = i0 + warp * RW + r;
        mylab[r] = labels[i];
        pcrow[r] = g_pcs + (long)i * NN;
    }

    float acc[RW], esum[RW];
#pragma unroll
    for (int r = 0; r < RW; r++) { acc[r] = 0.f; esum[r] = 0.f; }

    for (int t = 0; t < NN / 32; t++) {
        __syncthreads();
        {   // cooperative tile load: ks j-major, vsT d-major
            int j = tid >> 3, d4 = (tid & 7) * 4;
            float4 kv = *(const float4*)&g_ksort[(t * 32 + j) * CC + h * HCH + d4];
            *(float4*)&ks[j * PAD + d4] = kv;
            float4 vv = *(const float4*)&g_vsort[(t * 32 + j) * CC + h * HCH + d4];
            vsT[(d4 + 0) * PAD + j] = vv.x;
            vsT[(d4 + 1) * PAD + j] = vv.y;
            vsT[(d4 + 2) * PAD + j] = vv.z;
            vsT[(d4 + 3) * PAD + j] = vv.w;
            if (tid < 32) labt[tid] = g_labsort[t * 32 + tid];
        }
        __syncthreads();

        int lj = labt[lane];
        unsigned mask[RW];
        bool anyk = false;
#pragma unroll
        for (int r = 0; r < RW; r++) {
            mask[r] = __ballot_sync(0xffffffffu, lj == mylab[r]);
            anyk |= (mask[r] != 0);
        }
        float4 kr[8];
        if (anyk) {
            const float4* kp = (const float4*)&ks[lane * PAD];
#pragma unroll
            for (int dd = 0; dd < 8; dd++) kr[dd] = kp[dd];
        }
#pragma unroll
        for (int r = 0; r < RW; r++) {
            float pcv = pcrow[r][t * 32 + lane];
            float sc;
            if (mask[r]) {
                float dotv = 0.f;
                if (lj == mylab[r]) {
                    const float4* qp = (const float4*)&qs[(warp * RW + r) * PAD];
#pragma unroll
                    for (int dd = 0; dd < 8; dd++) {
                        float4 a = qp[dd];   // broadcast
                        dotv += a.x * kr[dd].x + a.y * kr[dd].y
                              + a.z * kr[dd].z + a.w * kr[dd].w;
                    }
                }
                sc = (lj == mylab[r]) ? dotv : cs[warp * RW + r][lj] * pcv;
            } else {
                sc = cs[warp * RW + r][lj] * pcv;
            }
            float e = __expf(sc);   // scores bounded; fixed-max softmax
            es[warp][r * 32 + lane] = e;
            esum[r] += e;
        }
        __syncwarp();
        const float4* vr = (const float4*)&vsT[lane * PAD];   // lane = dim d
#pragma unroll
        for (int r = 0; r < RW; r++) {
            const float4* er = (const float4*)&es[warp][r * 32];   // broadcast
#pragma unroll
            for (int jj = 0; jj < 8; jj++) {
                float4 ev = er[jj], vv = vr[jj];
                acc[r] += ev.x * vv.x + ev.y * vv.y + ev.z * vv.z + ev.w * vv.w;
            }
        }
        __syncwarp();
    }
#pragma unroll
    for (int r = 0; r < RW; r++) {
        float S = esum[r];
#pragma unroll
        for (int o = 16; o; o >>= 1) S += __shfl_xor_sync(0xffffffffu, S, o);
        int i = i0 + warp * RW + r;
        g_attn[i * CC + h * HCH + lane] = acc[r] / S;
    }
}

// ================= MLP stage A: h = leaky(x @ w + b)
__global__ __launch_bounds__(256) void mlp_a_kernel(
    const float* __restrict__ x, const float* __restrict__ w,
    const float* __restrict__ b, float* __restrict__ out, int transposed_in) {
    __shared__ float xs[32 * 129];
    int n0 = blockIdx.x * 32;
    int tid = threadIdx.x;
    if (transposed_in) {
        for (int idx = tid; idx < 32 * 128; idx += 256) {
            int nn = idx & 31, ci = idx >> 5;
            xs[nn * 129 + ci] = x[ci * NN + n0 + nn];
        }
    } else {
        for (int idx = tid; idx < 32 * 128; idx += 256) {
            int ci = idx & 127, nn = idx >> 7;
            xs[nn * 129 + ci] = x[(n0 + nn) * 128 + ci];
        }
    }
    __syncthreads();
    int co = tid;
    float acc[32];
#pragma unroll
    for (int n = 0; n < 32; n++) acc[n] = 0.f;
    for (int ci = 0; ci < 128; ci++) {
        float wv = w[ci * C2 + co];
#pragma unroll
        for (int n = 0; n < 32; n++) acc[n] += xs[n * 129 + ci] * wv;
    }
    float bv = b[co];
#pragma unroll
    for (int n = 0; n < 32; n++) {
        float y = acc[n] + bv;
        y = (y > 0.f) ? y : 0.01f * y;
        out[(n0 + n) * C2 + co] = y;
    }
}

// ================= MLP stage B + residual, writes channel-major [C][N]
__global__ __launch_bounds__(256) void mlp_b_kernel(
    const float* __restrict__ h1, const float* __restrict__ w,
    const float* __restrict__ b, const float* __restrict__ base,
    float* __restrict__ out, int base_chanmajor) {
    __shared__ float buf[32 * 257];
    int n0 = blockIdx.x * 32;
    int tid = threadIdx.x;
    for (int idx = tid; idx < 32 * 256; idx += 256) {
        int ci = idx & 255, nn = idx >> 8;
        buf[nn * 257 + ci] = h1[(n0 + nn) * C2 + ci];
    }
    __syncthreads();
    int co = tid & 127, half = tid >> 7;
    float acc[16];
#pragma unroll
    for (int n = 0; n < 16; n++) acc[n] = 0.f;
    for (int ci = 0; ci < 256; ci++) {
        float wv = w[ci * 128 + co];
#pragma unroll
        for (int n = 0; n < 16; n++) acc[n] += buf[(half * 16 + n) * 257 + ci] * wv;
    }
    __syncthreads();
    float bv = b[co];
    float* ys = buf;   // reuse as [32][129]
#pragma unroll
    for (int n = 0; n < 16; n++) {
        int nn = half * 16 + n;
        float y = acc[n] + bv;
        if (!base_chanmajor) y += base[(n0 + nn) * 128 + co];
        ys[nn * 129 + co] = y;
    }
    __syncthreads();
    for (int idx = tid; idx < 32 * 128; idx += 256) {
        int nn = idx & 31, c = idx >> 5;
        float y = ys[nn * 129 + c];
        if (base_chanmajor) y += base[c * NN + n0 + nn];
        out[c * NN + n0 + nn] = y;
    }
}

// ================= launch =================
extern "C" void kernel_launch(void* const* d_in, const int* in_sizes, int n_in,
                              void* d_out, int out_size) {
    const float* q_img = (const float*)d_in[0];
    const float* k_img = (const float*)d_in[1];
    const float* v_img = (const float*)d_in[2];
    const float* pc    = (const float*)d_in[3];

    // labels = unique input with exactly N=2304 elements
    int labIdx = -1;
    for (int i = 4; i < n_in; i++) if (in_sizes[i] == NN) { labIdx = i; break; }
    const int* labels = (const int*)d_in[labIdx];

    const float* wp[14]; int c = 0;
    for (int i = 4; i < n_in && c < 14; i++)
        if (i != labIdx) wp[c++] = (const float*)d_in[i];
    const float *wq = wp[0], *bq = wp[1], *wk = wp[2], *bk = wp[3];
    const float *wv = wp[4], *bv = wp[5];
    const float *w1a = wp[6], *b1a = wp[7], *w1b = wp[8], *b1b = wp[9];
    const float *w2a = wp[10], *b2a = wp[11], *w2b = wp[12], *b2b = wp[13];

    float *gq, *gk, *gv, *gattn, *gh1, *grs1;
    cudaGetSymbolAddress((void**)&gq, g_q);
    cudaGetSymbolAddress((void**)&gk, g_k);
    cudaGetSymbolAddress((void**)&gv, g_v);
    cudaGetSymbolAddress((void**)&gattn, g_attn);
    cudaGetSymbolAddress((void**)&gh1, g_h1);
    cudaGetSymbolAddress((void**)&grs1, g_rs1);

    // projections (q pre-scaled by 1/sqrt(HC))
    proj_kernel<<<NN / 32, 256>>>(q_img, wq, bq, gq, INV_SCALE);
    proj_kernel<<<NN / 32, 256>>>(k_img, wk, bk, gk, 1.0f);
    proj_kernel<<<NN / 32, 256>>>(v_img, wv, bv, gv, 1.0f);

    // cluster sort machinery
    sortidx_kernel<<<1, 256>>>(labels);
    gather_kv_kernel<<<NN * 32 / 256, 256>>>();
    pcsort_kernel<<<NN, 256>>>(pc);
    centers_kernel<<<KK, 128>>>();

    // fused attention over sorted keys
    attn_kernel<<<dim3(NN / 32, NHEAD), 256>>>(labels);

    // rs1 = v_spatial + mlp1(attn_out)      -> g_rs1 (channel-major)
    mlp_a_kernel<<<NN / 32, 256>>>(gattn, w1a, b1a, gh1, 0);
    mlp_b_kernel<<<NN / 32, 256>>>(gh1, w1b, b1b, gv, grs1, 0);

    // rs2 = rs1 + mlp2(rs1_flat)            -> d_out (channel-major)
    mlp_a_kernel<<<NN / 32, 256>>>(grs1, w2a, b2a, gh1, 1);
    mlp_b_kernel<<<NN / 32, 256>>>(gh1, w2b, b2b, grs1, (float*)d_out, 1);
}

// round 8
// speedup vs baseline: 1.1910x; 1.1910x over previous
#include <cuda_runtime.h>

#define NN 2304          // H*W
#define CC 128           // channels
#define KK 16            // clusters
#define NHEAD 4
#define HCH 32           // head channels
#define C2 256           // 2*C
#define EPSV 1e-6f
#define INV_SCALE 0.17677669529663687f   // 1/sqrt(32)

// -------- scratch (device globals; no allocation allowed) --------
__device__ float g_q[NN * CC];       // scaled by 1/sqrt(HC)
__device__ float g_k[NN * CC];
__device__ float g_v[NN * CC];
__device__ float g_ksort[NN * CC];   // k rows permuted into cluster order
__device__ float g_vsort[NN * CC];
__device__ float g_pcs[NN * NN];     // pc columns permuted into cluster order
__device__ int   g_perm[NN];         // sorted pos -> original index
__device__ int   g_labsort[NN];      // label at sorted pos
__device__ int   g_coff[KK + 1];     // cluster offsets in sorted order
__device__ float g_cent[KK * CC];
__device__ float g_attn[NN * CC];    // attention out, [N][C], C = h*32+d
__device__ float g_h1[NN * C2];
__device__ float g_rs1[NN * CC];     // channel-major [C][N]

// ================= projection: out[n][co] = (sum_ci img[ci][n]*w[ci][co]+b[co])*scale
__global__ __launch_bounds__(256) void proj_kernel(
    const float* __restrict__ img, const float* __restrict__ w,
    const float* __restrict__ b, float* __restrict__ out, float scale) {
    __shared__ float xs[32 * 129];
    int n0 = blockIdx.x * 32;
    int tid = threadIdx.x;
    for (int idx = tid; idx < 32 * 128; idx += 256) {
        int nn = idx & 31, ci = idx >> 5;
        xs[nn * 129 + ci] = img[ci * NN + n0 + nn];
    }
    __syncthreads();
    int co = tid & 127, half = tid >> 7;
    float acc[16];
#pragma unroll
    for (int n = 0; n < 16; n++) acc[n] = 0.f;
    for (int ci = 0; ci < 128; ci++) {
        float wv = w[ci * 128 + co];
#pragma unroll
        for (int n = 0; n < 16; n++) acc[n] += xs[(half * 16 + n) * 129 + ci] * wv;
    }
    float bv = b[co];
#pragma unroll
    for (int n = 0; n < 16; n++)
        out[(n0 + half * 16 + n) * CC + co] = (acc[n] + bv) * scale;
}

// ================= stable counting sort of labels (single block, 256 threads)
// cnt padded to 17 -> per-thread rows hit different banks (stride 17 is odd)
#define CHUNK 9   // 256*9 = 2304
__global__ __launch_bounds__(256) void sortidx_kernel(const int* __restrict__ labels) {
    __shared__ int labs[NN];
    __shared__ int cnt[256][KK + 1];
    __shared__ int tot[KK], coff[KK + 1];
    int tid = threadIdx.x;
    for (int i = tid; i < NN; i += 256) labs[i] = labels[i];
#pragma unroll
    for (int k = 0; k < KK; k++) cnt[tid][k] = 0;
    __syncthreads();
    int base = tid * CHUNK;
#pragma unroll
    for (int c = 0; c < CHUNK; c++) cnt[tid][labs[base + c]]++;
    __syncthreads();
    if (tid < KK) {
        int s = 0;
        for (int t = 0; t < 256; t++) s += cnt[t][tid];
        tot[tid] = s;
    }
    __syncthreads();
    if (tid == 0) {
        int s = 0;
        for (int k = 0; k < KK; k++) { coff[k] = s; s += tot[k]; }
        coff[KK] = s;
        for (int k = 0; k <= KK; k++) g_coff[k] = coff[k];
    }
    __syncthreads();
    if (tid < KK) {   // turn cnt[t][k] into absolute start positions
        int run = coff[tid];
        for (int t = 0; t < 256; t++) {
            int c = cnt[t][tid];
            cnt[t][tid] = run;
            run += c;
        }
    }
    __syncthreads();
#pragma unroll
    for (int c = 0; c < CHUNK; c++) {
        int n = base + c;
        int k = labs[n];
        int pos = cnt[tid][k]++;
        g_perm[pos] = n;
        g_labsort[pos] = k;
    }
}

// ================= gather k,v rows into sorted order (warp per row, coalesced)
__global__ __launch_bounds__(256) void gather_kv_kernel() {
    int idx = blockIdx.x * 256 + threadIdx.x;   // NN*32 threads
    int pos = idx >> 5, f = idx & 31;
    int j = g_perm[pos];
    ((float4*)g_ksort)[pos * 32 + f] = ((const float4*)g_k)[j * 32 + f];
    ((float4*)g_vsort)[pos * 32 + f] = ((const float4*)g_v)[j * 32 + f];
}

// ================= permute pc columns into sorted order (block per query row)
__global__ __launch_bounds__(256) void pcsort_kernel(const float* __restrict__ pc) {
    __shared__ float row[NN];
    int i = blockIdx.x, tid = threadIdx.x;
    const float* src = pc + (long)i * NN;
    for (int j = tid; j < NN; j += 256) row[j] = src[j];
    __syncthreads();
    float* dst = g_pcs + (long)i * NN;
    for (int p = tid; p < NN; p += 256) dst[p] = row[g_perm[p]];
}

// ================= cluster centers from sorted k: 4 parallel quarters + ordered combine
__global__ __launch_bounds__(512) void centers_kernel() {
    __shared__ float part[4][128];
    int k = blockIdx.x;
    int g = threadIdx.x >> 7, ch = threadIdx.x & 127;
    int s = g_coff[k], e = g_coff[k + 1];
    int len = e - s;
    int q0 = s + (len * g) / 4, q1 = s + (len * (g + 1)) / 4;
    float sum = 0.f;
    for (int p = q0; p < q1; p++) sum += g_ksort[p * CC + ch];
    part[g][ch] = sum;
    __syncthreads();
    if (g == 0) {
        float tot = ((part[0][ch] + part[1][ch]) + part[2][ch]) + part[3][ch];
        g_cent[k * CC + ch] = tot / ((float)len + EPSV);
    }
}

// ================= fused clustered attention over sorted keys
// 256 threads = 8 warps; warp owns 4 query rows; fixed-max softmax;
// double-buffered k/v/pc/label tiles hide L2 latency behind compute.
#define RW 4
#define PAD 36   // 9 float4s/row -> odd float4 stride -> conflict-free LDS.128
#define NT (NN / 32)   // 72 tiles
__global__ __launch_bounds__(256) void attn_kernel(const int* __restrict__ labels) {
    __shared__ float qs[32 * PAD];
    __shared__ float cens[KK * PAD];
    __shared__ float cs[32][KK];
    __shared__ float ks[2][32 * PAD];    // [buf][j][d]
    __shared__ float vsT[2][32 * PAD];   // [buf][d][j]
    __shared__ float es[8][RW * 32];     // per-warp exp weights
    __shared__ int labt[2][32];

    int h = blockIdx.y;
    int i0 = blockIdx.x * 32;
    int tid = threadIdx.x;
    int warp = tid >> 5, lane = tid & 31;
    int hoff = h * HCH;

    {   // q tile (32 rows) + centers (16 rows), float4 loads
        int r = tid >> 3, d4 = (tid & 7) * 4;
        *(float4*)&qs[r * PAD + d4] = *(const float4*)&g_q[(i0 + r) * CC + hoff + d4];
        if (tid < KK * 8)
            *(float4*)&cens[r * PAD + d4] = *(const float4*)&g_cent[r * CC + hoff + d4];
    }
    __syncthreads();
#pragma unroll
    for (int p = 0; p < 2; p++) {   // cs[r][t] = q_r . center_t
        int task = tid + 256 * p;
        int r = task >> 4, t = task & 15;
        float s = 0.f;
#pragma unroll
        for (int d = 0; d < 32; d++) s += qs[r * PAD + d] * cens[t * PAD + d];
        cs[r][t] = s;
    }

    int mylab[RW];
    const float* pcrow[RW];
#pragma unroll
    for (int r = 0; r < RW; r++) {
        int i = i0 + warp * RW + r;
        mylab[r] = labels[i];
        pcrow[r] = g_pcs + (long)i * NN;
    }

    // tile-load lane roles
    int tj = tid >> 3, td4 = (tid & 7) * 4;

    // ---- prologue: fetch tile 0 ----
    float4 kf = *(const float4*)&g_ksort[tj * CC + hoff + td4];
    float4 vf = *(const float4*)&g_vsort[tj * CC + hoff + td4];
    int lb = (tid < 32) ? g_labsort[tid] : 0;
    float pcn[RW];
#pragma unroll
    for (int r = 0; r < RW; r++) pcn[r] = pcrow[r][lane];

    {   // store tile 0 into buffer 0
        *(float4*)&ks[0][tj * PAD + td4] = kf;
        vsT[0][(td4 + 0) * PAD + tj] = vf.x;
        vsT[0][(td4 + 1) * PAD + tj] = vf.y;
        vsT[0][(td4 + 2) * PAD + tj] = vf.z;
        vsT[0][(td4 + 3) * PAD + tj] = vf.w;
        if (tid < 32) labt[0][tid] = lb;
    }

    float acc[RW], esum[RW];
#pragma unroll
    for (int r = 0; r < RW; r++) { acc[r] = 0.f; esum[r] = 0.f; }

    for (int t = 0; t < NT; t++) {
        int b = t & 1;
        __syncthreads();   // buffer b (stored last iteration / prologue) visible

        float pccur[RW];
#pragma unroll
        for (int r = 0; r < RW; r++) pccur[r] = pcn[r];

        if (t + 1 < NT) {   // prefetch next tile into registers
            int nbase = (t + 1) * 32;
            kf = *(const float4*)&g_ksort[(nbase + tj) * CC + hoff + td4];
            vf = *(const float4*)&g_vsort[(nbase + tj) * CC + hoff + td4];
            if (tid < 32) lb = g_labsort[nbase + tid];
#pragma unroll
            for (int r = 0; r < RW; r++) pcn[r] = pcrow[r][nbase + lane];
        }

        // ---- compute on buffer b ----
        int lj = labt[b][lane];
        unsigned mask[RW];
        bool anyk = false;
#pragma unroll
        for (int r = 0; r < RW; r++) {
            mask[r] = __ballot_sync(0xffffffffu, lj == mylab[r]);
            anyk |= (mask[r] != 0);
        }
        float4 kr[8];
        if (anyk) {
            const float4* kp = (const float4*)&ks[b][lane * PAD];
#pragma unroll
            for (int dd = 0; dd < 8; dd++) kr[dd] = kp[dd];
        }
#pragma unroll
        for (int r = 0; r < RW; r++) {
            float sc;
            if (mask[r]) {
                float dotv = 0.f;
                if (lj == mylab[r]) {
                    const float4* qp = (const float4*)&qs[(warp * RW + r) * PAD];
#pragma unroll
                    for (int dd = 0; dd < 8; dd++) {
                        float4 a = qp[dd];   // broadcast
                        dotv += a.x * kr[dd].x + a.y * kr[dd].y
                              + a.z * kr[dd].z + a.w * kr[dd].w;
                    }
                }
                sc = (lj == mylab[r]) ? dotv : cs[warp * RW + r][lj] * pccur[r];
            } else {
                sc = cs[warp * RW + r][lj] * pccur[r];
            }
            float e = __expf(sc);   // scores bounded; fixed-max softmax
            es[warp][r * 32 + lane] = e;
            esum[r] += e;
        }
        __syncwarp();
        // loop-interchanged accumulate: vv loaded once, reused for all 4 rows
        const float4* vr = (const float4*)&vsT[b][lane * PAD];   // lane = dim d
#pragma unroll
        for (int jj = 0; jj < 8; jj++) {
            float4 vv = vr[jj];
#pragma unroll
            for (int r = 0; r < RW; r++) {
                float4 ev = *(const float4*)&es[warp][r * 32 + jj * 4];  // broadcast
                acc[r] += ev.x * vv.x + ev.y * vv.y + ev.z * vv.z + ev.w * vv.w;
            }
        }
        __syncwarp();

        // ---- stage next tile into the other buffer ----
        if (t + 1 < NT) {
            int nb = b ^ 1;
            *(float4*)&ks[nb][tj * PAD + td4] = kf;
            vsT[nb][(td4 + 0) * PAD + tj] = vf.x;
            vsT[nb][(td4 + 1) * PAD + tj] = vf.y;
            vsT[nb][(td4 + 2) * PAD + tj] = vf.z;
            vsT[nb][(td4 + 3) * PAD + tj] = vf.w;
            if (tid < 32) labt[nb][tid] = lb;
        }
    }
#pragma unroll
    for (int r = 0; r < RW; r++) {
        float S = esum[r];
#pragma unroll
        for (int o = 16; o; o >>= 1) S += __shfl_xor_sync(0xffffffffu, S, o);
        int i = i0 + warp * RW + r;
        g_attn[i * CC + hoff + lane] = acc[r] / S;
    }
}

// ================= MLP stage A: h = leaky(x @ w + b)
__global__ __launch_bounds__(256) void mlp_a_kernel(
    const float* __restrict__ x, const float* __restrict__ w,
    const float* __restrict__ b, float* __restrict__ out, int transposed_in) {
    __shared__ float xs[32 * 129];
    int n0 = blockIdx.x * 32;
    int tid = threadIdx.x;
    if (transposed_in) {
        for (int idx = tid; idx < 32 * 128; idx += 256) {
            int nn = idx & 31, ci = idx >> 5;
            xs[nn * 129 + ci] = x[ci * NN + n0 + nn];
        }
    } else {
        for (int idx = tid; idx < 32 * 128; idx += 256) {
            int ci = idx & 127, nn = idx >> 7;
            xs[nn * 129 + ci] = x[(n0 + nn) * 128 + ci];
        }
    }
    __syncthreads();
    int co = tid;
    float acc[32];
#pragma unroll
    for (int n = 0; n < 32; n++) acc[n] = 0.f;
    for (int ci = 0; ci < 128; ci++) {
        float wv = w[ci * C2 + co];
#pragma unroll
        for (int n = 0; n < 32; n++) acc[n] += xs[n * 129 + ci] * wv;
    }
    float bv = b[co];
#pragma unroll
    for (int n = 0; n < 32; n++) {
        float y = acc[n] + bv;
        y = (y > 0.f) ? y : 0.01f * y;
        out[(n0 + n) * C2 + co] = y;
    }
}

// ================= MLP stage B + residual, writes channel-major [C][N]
__global__ __launch_bounds__(256) void mlp_b_kernel(
    const float* __restrict__ h1, const float* __restrict__ w,
    const float* __restrict__ b, const float* __restrict__ base,
    float* __restrict__ out, int base_chanmajor) {
    __shared__ float buf[32 * 257];
    int n0 = blockIdx.x * 32;
    int tid = threadIdx.x;
    for (int idx = tid; idx < 32 * 256; idx += 256) {
        int ci = idx & 255, nn = idx >> 8;
        buf[nn * 257 + ci] = h1[(n0 + nn) * C2 + ci];
    }
    __syncthreads();
    int co = tid & 127, half = tid >> 7;
    float acc[16];
#pragma unroll
    for (int n = 0; n < 16; n++) acc[n] = 0.f;
    for (int ci = 0; ci < 256; ci++) {
        float wv = w[ci * 128 + co];
#pragma unroll
        for (int n = 0; n < 16; n++) acc[n] += buf[(half * 16 + n) * 257 + ci] * wv;
    }
    __syncthreads();
    float bv = b[co];
    float* ys = buf;   // reuse as [32][129]
#pragma unroll
    for (int n = 0; n < 16; n++) {
        int nn = half * 16 + n;
        float y = acc[n] + bv;
        if (!base_chanmajor) y += base[(n0 + nn) * 128 + co];
        ys[nn * 129 + co] = y;
    }
    __syncthreads();
    for (int idx = tid; idx < 32 * 128; idx += 256) {
        int nn = idx & 31, c = idx >> 5;
        float y = ys[nn * 129 + c];
        if (base_chanmajor) y += base[c * NN + n0 + nn];
        out[c * NN + n0 + nn] = y;
    }
}

// ================= launch =================
extern "C" void kernel_launch(void* const* d_in, const int* in_sizes, int n_in,
                              void* d_out, int out_size) {
    const float* q_img = (const float*)d_in[0];
    const float* k_img = (const float*)d_in[1];
    const float* v_img = (const float*)d_in[2];
    const float* pc    = (const float*)d_in[3];

    // labels = unique input with exactly N=2304 elements
    int labIdx = -1;
    for (int i = 4; i < n_in; i++) if (in_sizes[i] == NN) { labIdx = i; break; }
    const int* labels = (const int*)d_in[labIdx];

    const float* wp[14]; int c = 0;
    for (int i = 4; i < n_in && c < 14; i++)
        if (i != labIdx) wp[c++] = (const float*)d_in[i];
    const float *wq = wp[0], *bq = wp[1], *wk = wp[2], *bk = wp[3];
    const float *wv = wp[4], *bv = wp[5];
    const float *w1a = wp[6], *b1a = wp[7], *w1b = wp[8], *b1b = wp[9];
    const float *w2a = wp[10], *b2a = wp[11], *w2b = wp[12], *b2b = wp[13];

    float *gq, *gk, *gv, *gattn, *gh1, *grs1;
    cudaGetSymbolAddress((void**)&gq, g_q);
    cudaGetSymbolAddress((void**)&gk, g_k);
    cudaGetSymbolAddress((void**)&gv, g_v);
    cudaGetSymbolAddress((void**)&gattn, g_attn);
    cudaGetSymbolAddress((void**)&gh1, g_h1);
    cudaGetSymbolAddress((void**)&grs1, g_rs1);

    // projections (q pre-scaled by 1/sqrt(HC))
    proj_kernel<<<NN / 32, 256>>>(q_img, wq, bq, gq, INV_SCALE);
    proj_kernel<<<NN / 32, 256>>>(k_img, wk, bk, gk, 1.0f);
    proj_kernel<<<NN / 32, 256>>>(v_img, wv, bv, gv, 1.0f);

    // cluster sort machinery
    sortidx_kernel<<<1, 256>>>(labels);
    gather_kv_kernel<<<NN * 32 / 256, 256>>>();
    pcsort_kernel<<<NN, 256>>>(pc);
    centers_kernel<<<KK, 512>>>();

    // fused attention over sorted keys
    attn_kernel<<<dim3(NN / 32, NHEAD), 256>>>(labels);

    // rs1 = v_spatial + mlp1(attn_out)      -> g_rs1 (channel-major)
    mlp_a_kernel<<<NN / 32, 256>>>(gattn, w1a, b1a, gh1, 0);
    mlp_b_kernel<<<NN / 32, 256>>>(gh1, w1b, b1b, gv, grs1, 0);

    // rs2 = rs1 + mlp2(rs1_flat)            -> d_out (channel-major)
    mlp_a_kernel<<<NN / 32, 256>>>(grs1, w2a, b2a, gh1, 1);
    mlp_b_kernel<<<NN / 32, 256>>>(gh1, w2b, b2b, grs1, (float*)d_out, 1);
}

// round 11
// speedup vs baseline: 1.2013x; 1.0086x over previous
#include <cuda_runtime.h>

#define NN 2304          // H*W
#define CC 128           // channels
#define KK 16            // clusters
#define NHEAD 4
#define HCH 32           // head channels
#define C2 256           // 2*C
#define EPSV 1e-6f
#define INV_SCALE 0.17677669529663687f   // 1/sqrt(32)

// -------- scratch (device globals; no allocation allowed) --------
__device__ float g_q[NN * CC];       // scaled by 1/sqrt(HC)
__device__ float g_k[NN * CC];
__device__ float g_v[NN * CC];
__device__ float g_ksort[NN * CC];   // k rows permuted into cluster order
__device__ float g_vsort[NN * CC];
__device__ float g_pcs[NN * NN];     // pc columns permuted into cluster order
__device__ int   g_perm[NN];         // sorted pos -> original index
__device__ int   g_labsort[NN];      // label at sorted pos
__device__ int   g_coff[KK + 1];     // cluster offsets in sorted order
__device__ float g_cent[KK * CC];
__device__ float g_accp[2 * NN * CC];       // split-K partial weighted sums
__device__ float g_esump[2 * NN * NHEAD];   // split-K partial softmax denoms
__device__ float g_rs1[NN * CC];     // channel-major [C][N]

// ================= fused triple projection (blockIdx.y selects q/k/v)
__global__ __launch_bounds__(256) void proj3_kernel(
    const float* __restrict__ qi, const float* __restrict__ ki, const float* __restrict__ vi,
    const float* __restrict__ wq, const float* __restrict__ bq,
    const float* __restrict__ wk, const float* __restrict__ bk,
    const float* __restrict__ wv, const float* __restrict__ bv) {
    int which = blockIdx.y;
    const float* img = which == 0 ? qi : which == 1 ? ki : vi;
    const float* w   = which == 0 ? wq : which == 1 ? wk : wv;
    const float* b   = which == 0 ? bq : which == 1 ? bk : bv;
    float* out       = which == 0 ? g_q : which == 1 ? g_k : g_v;
    float scale      = which == 0 ? INV_SCALE : 1.0f;

    __shared__ float xs[32 * 129];
    int n0 = blockIdx.x * 32;
    int tid = threadIdx.x;
    for (int idx = tid; idx < 32 * 128; idx += 256) {
        int nn = idx & 31, ci = idx >> 5;
        xs[nn * 129 + ci] = img[ci * NN + n0 + nn];
    }
    __syncthreads();
    int co = tid & 127, half = tid >> 7;
    float acc[16];
#pragma unroll
    for (int n = 0; n < 16; n++) acc[n] = 0.f;
    for (int ci = 0; ci < 128; ci++) {
        float wv2 = w[ci * 128 + co];
#pragma unroll
        for (int n = 0; n < 16; n++) acc[n] += xs[(half * 16 + n) * 129 + ci] * wv2;
    }
    float bv2 = b[co];
#pragma unroll
    for (int n = 0; n < 16; n++)
        out[(n0 + half * 16 + n) * CC + co] = (acc[n] + bv2) * scale;
}

// ================= stable counting sort, parallel warp-scan version (512 thr)
#define CHUNK 9   // 256*9 = 2304
__global__ __launch_bounds__(512) void sortidx_kernel(const int* __restrict__ labels) {
    __shared__ int labs[NN];
    __shared__ int cnt[256][KK + 1];
    __shared__ int tot[KK], coff[KK + 1];
    int tid = threadIdx.x;
    for (int i = tid; i < NN; i += 512) labs[i] = labels[i];
    if (tid < 256) {
#pragma unroll
        for (int k = 0; k < KK; k++) cnt[tid][k] = 0;
    }
    __syncthreads();
    if (tid < 256) {
        int base = tid * CHUNK;
#pragma unroll
        for (int c = 0; c < CHUNK; c++) cnt[tid][labs[base + c]]++;
    }
    __syncthreads();
    int warp = tid >> 5, lane = tid & 31;
    {   // warp k computes exclusive running offsets over the 256 thread-counts
        int k = warp;   // 16 warps == 16 clusters
        int run = 0;
#pragma unroll
        for (int g = 0; g < 8; g++) {
            int t = g * 32 + lane;
            int c = cnt[t][k];
            int x = c;
#pragma unroll
            for (int off = 1; off < 32; off <<= 1) {
                int y = __shfl_up_sync(0xffffffffu, x, off);
                if (lane >= off) x += y;
            }
            cnt[t][k] = run + (x - c);      // exclusive within-cluster offset
            run += __shfl_sync(0xffffffffu, x, 31);
        }
        if (lane == 0) tot[k] = run;
    }
    __syncthreads();
    if (tid == 0) {   // tiny 16-element scan
        int s = 0;
        for (int k = 0; k < KK; k++) { coff[k] = s; s += tot[k]; }
        coff[KK] = s;
        for (int k = 0; k <= KK; k++) g_coff[k] = coff[k];
    }
    __syncthreads();
    {   // add cluster base offsets
        int k = warp;
        int ck = coff[k];
#pragma unroll
        for (int g = 0; g < 8; g++) cnt[g * 32 + lane][k] += ck;
    }
    __syncthreads();
    if (tid < 256) {
        int base = tid * CHUNK;
#pragma unroll
        for (int c = 0; c < CHUNK; c++) {
            int n = base + c;
            int k = labs[n];
            int pos = cnt[tid][k]++;
            g_perm[pos] = n;
            g_labsort[pos] = k;
        }
    }
}

// ================= fused prep: pc column-permute + kv gather + centers
#define GATHER_BLOCKS (NN * 32 / 256)   // 288
__global__ __launch_bounds__(256) void prep_kernel(
    const float* __restrict__ pc, const int* __restrict__ labels) {
    __shared__ float row[NN];
    __shared__ float part[2][128];
    int bid = blockIdx.x, tid = threadIdx.x;

    if (bid < NN) {   // ---- permute one pc row's columns into sorted order
        const float* src = pc + (long)bid * NN;
        for (int j = tid; j < NN; j += 256) row[j] = src[j];
        __syncthreads();
        float* dst = g_pcs + (long)bid * NN;
        for (int p = tid; p < NN; p += 256) dst[p] = row[g_perm[p]];
    } else if (bid < NN + GATHER_BLOCKS) {   // ---- gather k,v rows
        int idx = (bid - NN) * 256 + tid;
        int pos = idx >> 5, f = idx & 31;
        int j = g_perm[pos];
        ((float4*)g_ksort)[pos * 32 + f] = ((const float4*)g_k)[j * 32 + f];
        ((float4*)g_vsort)[pos * 32 + f] = ((const float4*)g_v)[j * 32 + f];
    } else {   // ---- centers from UNSORTED k (independent of gather)
        int k = bid - NN - GATHER_BLOCKS;
        int g = tid >> 7, ch = tid & 127;
        int h0 = g * (NN / 2), h1 = h0 + NN / 2;
        float sum = 0.f;
        for (int n = h0; n < h1; n++)
            if (labels[n] == k) sum += g_k[n * CC + ch];
        part[g][ch] = sum;
        __syncthreads();
        if (g == 0) {
            int len = g_coff[k + 1] - g_coff[k];
            g_cent[k * CC + ch] = (part[0][ch] + part[1][ch]) / ((float)len + EPSV);
        }
    }
}

// ================= fused clustered attention, split-K=2 over sorted keys
// grid (NN/32, NHEAD, 2); 256 thr = 8 warps x 4 rows; fixed-max softmax.
#define RW 4
#define PAD 36   // 9 float4s/row -> odd float4 stride -> conflict-free LDS.128
#define NT (NN / 32)   // 72 tiles
__global__ __launch_bounds__(256) void attn_kernel(const int* __restrict__ labels) {
    __shared__ float qs[32 * PAD];
    __shared__ float cens[KK * PAD];
    __shared__ float cs[32][KK];
    __shared__ float ks[2][32 * PAD];    // [buf][j][d]
    __shared__ float vsT[2][32 * PAD];   // [buf][d][j]
    __shared__ float es[8][RW * 32];     // per-warp exp weights
    __shared__ int labt[2][32];

    int h = blockIdx.y;
    int z = blockIdx.z;
    int i0 = blockIdx.x * 32;
    int tid = threadIdx.x;
    int warp = tid >> 5, lane = tid & 31;
    int hoff = h * HCH;
    int t0 = z * (NT / 2), t1 = t0 + NT / 2;

    {   // q tile + centers
        int r = tid >> 3, d4 = (tid & 7) * 4;
        *(float4*)&qs[r * PAD + d4] = *(const float4*)&g_q[(i0 + r) * CC + hoff + d4];
        if (tid < KK * 8)
            *(float4*)&cens[r * PAD + d4] = *(const float4*)&g_cent[r * CC + hoff + d4];
    }
    __syncthreads();
#pragma unroll
    for (int p = 0; p < 2; p++) {   // cs[r][t] = q_r . center_t
        int task = tid + 256 * p;
        int r = task >> 4, t = task & 15;
        float s = 0.f;
#pragma unroll
        for (int d = 0; d < 32; d++) s += qs[r * PAD + d] * cens[t * PAD + d];
        cs[r][t] = s;
    }

    int mylab[RW];
    const float* pcrow[RW];
#pragma unroll
    for (int r = 0; r < RW; r++) {
        int i = i0 + warp * RW + r;
        mylab[r] = labels[i];
        pcrow[r] = g_pcs + (long)i * NN;
    }

    int tj = tid >> 3, td4 = (tid & 7) * 4;

    // ---- prologue: fetch tile t0 ----
    float4 kf = *(const float4*)&g_ksort[(t0 * 32 + tj) * CC + hoff + td4];
    float4 vf = *(const float4*)&g_vsort[(t0 * 32 + tj) * CC + hoff + td4];
    int lb = (tid < 32) ? g_labsort[t0 * 32 + tid] : 0;
    float pcn[RW];
#pragma unroll
    for (int r = 0; r < RW; r++) pcn[r] = pcrow[r][t0 * 32 + lane];

    {
        *(float4*)&ks[0][tj * PAD + td4] = kf;
        vsT[0][(td4 + 0) * PAD + tj] = vf.x;
        vsT[0][(td4 + 1) * PAD + tj] = vf.y;
        vsT[0][(td4 + 2) * PAD + tj] = vf.z;
        vsT[0][(td4 + 3) * PAD + tj] = vf.w;
        if (tid < 32) labt[0][tid] = lb;
    }

    float acc[RW], esum[RW];
#pragma unroll
    for (int r = 0; r < RW; r++) { acc[r] = 0.f; esum[r] = 0.f; }

    for (int t = t0; t < t1; t++) {
        int b = (t - t0) & 1;
        __syncthreads();

        float pccur[RW];
#pragma unroll
        for (int r = 0; r < RW; r++) pccur[r] = pcn[r];

        if (t + 1 < t1) {   // register prefetch of next tile
            int nbase = (t + 1) * 32;
            kf = *(const float4*)&g_ksort[(nbase + tj) * CC + hoff + td4];
            vf = *(const float4*)&g_vsort[(nbase + tj) * CC + hoff + td4];
            if (tid < 32) lb = g_labsort[nbase + tid];
#pragma unroll
            for (int r = 0; r < RW; r++) pcn[r] = pcrow[r][nbase + lane];
        }

        int lj = labt[b][lane];
        unsigned mask[RW];
        bool anyk = false;
#pragma unroll
        for (int r = 0; r < RW; r++) {
            mask[r] = __ballot_sync(0xffffffffu, lj == mylab[r]);
            anyk |= (mask[r] != 0);
        }
        float4 kr[8];
        if (anyk) {
            const float4* kp = (const float4*)&ks[b][lane * PAD];
#pragma unroll
            for (int dd = 0; dd < 8; dd++) kr[dd] = kp[dd];
        }
#pragma unroll
        for (int r = 0; r < RW; r++) {
            float sc;
            if (mask[r]) {
                float dotv = 0.f;
                if (lj == mylab[r]) {
                    const float4* qp = (const float4*)&qs[(warp * RW + r) * PAD];
#pragma unroll
                    for (int dd = 0; dd < 8; dd++) {
                        float4 a = qp[dd];
                        dotv += a.x * kr[dd].x + a.y * kr[dd].y
                              + a.z * kr[dd].z + a.w * kr[dd].w;
                    }
                }
                sc = (lj == mylab[r]) ? dotv : cs[warp * RW + r][lj] * pccur[r];
            } else {
                sc = cs[warp * RW + r][lj] * pccur[r];
            }
            float e = __expf(sc);   // bounded scores; fixed-max softmax
            es[warp][r * 32 + lane] = e;
            esum[r] += e;
        }
        __syncwarp();
        const float4* vr = (const float4*)&vsT[b][lane * PAD];
#pragma unroll
        for (int jj = 0; jj < 8; jj++) {
            float4 vv = vr[jj];
#pragma unroll
            for (int r = 0; r < RW; r++) {
                float4 ev = *(const float4*)&es[warp][r * 32 + jj * 4];
                acc[r] += ev.x * vv.x + ev.y * vv.y + ev.z * vv.z + ev.w * vv.w;
            }
        }
        __syncwarp();

        if (t + 1 < t1) {
            int nb = b ^ 1;
            *(float4*)&ks[nb][tj * PAD + td4] = kf;
            vsT[nb][(td4 + 0) * PAD + tj] = vf.x;
            vsT[nb][(td4 + 1) * PAD + tj] = vf.y;
            vsT[nb][(td4 + 2) * PAD + tj] = vf.z;
            vsT[nb][(td4 + 3) * PAD + tj] = vf.w;
            if (tid < 32) labt[nb][tid] = lb;
        }
    }
#pragma unroll
    for (int r = 0; r < RW; r++) {
        float S = esum[r];
#pragma unroll
        for (int o = 16; o; o >>= 1) S += __shfl_xor_sync(0xffffffffu, S, o);
        int i = i0 + warp * RW + r;
        g_accp[z * NN * CC + i * CC + hoff + lane] = acc[r];
        if (lane == 0) g_esump[z * NN * NHEAD + i * NHEAD + h] = S;
    }
}

// ================= fused MLP: stage A -> smem -> stage B + residual
// stage 0: x = combined attention out, base = v (n-major),   out = rs1 (chan-major)
// stage 1: x = rs1 (chan-major),       base = rs1 (chan-major), out = d_out
__global__ __launch_bounds__(256) void mlp_fused_kernel(
    const float* __restrict__ wa, const float* __restrict__ ba,
    const float* __restrict__ wb, const float* __restrict__ bb,
    const float* __restrict__ base, float* __restrict__ out, int stage) {
    __shared__ float xs[32 * 129];
    __shared__ float hs[32 * 257];
    int n0 = blockIdx.x * 32;
    int tid = threadIdx.x;

    if (stage == 0) {
        for (int idx = tid; idx < 32 * 128; idx += 256) {
            int ci = idx & 127, nn = idx >> 7;
            int i = n0 + nn, h = ci >> 5;
            float s = g_esump[i * NHEAD + h] + g_esump[NN * NHEAD + i * NHEAD + h];
            float a = g_accp[i * CC + ci] + g_accp[NN * CC + i * CC + ci];
            xs[nn * 129 + ci] = a / s;
        }
    } else {
        for (int idx = tid; idx < 32 * 128; idx += 256) {
            int nn = idx & 31, ci = idx >> 5;
            xs[nn * 129 + ci] = g_rs1[ci * NN + n0 + nn];
        }
    }
    __syncthreads();

    {   // stage A: hidden = leaky(x @ wa + ba), 256 hidden channels
        int co = tid;
        float acc[32];
#pragma unroll
        for (int n = 0; n < 32; n++) acc[n] = 0.f;
        for (int ci = 0; ci < 128; ci++) {
            float wv = wa[ci * C2 + co];
#pragma unroll
            for (int n = 0; n < 32; n++) acc[n] += xs[n * 129 + ci] * wv;
        }
        float bv = ba[co];
#pragma unroll
        for (int n = 0; n < 32; n++) {
            float y = acc[n] + bv;
            y = (y > 0.f) ? y : 0.01f * y;
            hs[n * 257 + co] = y;
        }
    }
    __syncthreads();

    {   // stage B: y = hidden @ wb + bb (+ residual), write chan-major
        int co = tid & 127, half = tid >> 7;
        float acc[16];
#pragma unroll
        for (int n = 0; n < 16; n++) acc[n] = 0.f;
        for (int ci = 0; ci < 256; ci++) {
            float wv = wb[ci * 128 + co];
#pragma unroll
            for (int n = 0; n < 16; n++) acc[n] += hs[(half * 16 + n) * 257 + ci] * wv;
        }
        float bv = bb[co];
        float* ys = xs;   // reuse (stage-A reads of xs are behind the barrier)
#pragma unroll
        for (int n = 0; n < 16; n++) {
            int nn = half * 16 + n;
            float y = acc[n] + bv;
            if (stage == 0) y += base[(n0 + nn) * CC + co];   // v, n-major
            ys[nn * 129 + co] = y;
        }
    }
    __syncthreads();
    for (int idx = tid; idx < 32 * 128; idx += 256) {
        int nn = idx & 31, c = idx >> 5;
        float y = xs[nn * 129 + c];
        if (stage == 1) y += base[c * NN + n0 + nn];   // rs1, chan-major
        out[c * NN + n0 + nn] = y;
    }
}

// ================= launch =================
extern "C" void kernel_launch(void* const* d_in, const int* in_sizes, int n_in,
                              void* d_out, int out_size) {
    const float* q_img = (const float*)d_in[0];
    const float* k_img = (const float*)d_in[1];
    const float* v_img = (const float*)d_in[2];
    const float* pc    = (const float*)d_in[3];

    // labels = unique input with exactly N=2304 elements
    int labIdx = -1;
    for (int i = 4; i < n_in; i++) if (in_sizes[i] == NN) { labIdx = i; break; }
    const int* labels = (const int*)d_in[labIdx];

    const float* wp[14]; int c = 0;
    for (int i = 4; i < n_in && c < 14; i++)
        if (i != labIdx) wp[c++] = (const float*)d_in[i];
    const float *wq = wp[0], *bq = wp[1], *wk = wp[2], *bk = wp[3];
    const float *wv = wp[4], *bv = wp[5];
    const float *w1a = wp[6], *b1a = wp[7], *w1b = wp[8], *b1b = wp[9];
    const float *w2a = wp[10], *b2a = wp[11], *w2b = wp[12], *b2b = wp[13];

    float *gv, *grs1;
    cudaGetSymbolAddress((void**)&gv, g_v);
    cudaGetSymbolAddress((void**)&grs1, g_rs1);

    // 1: all three projections (q pre-scaled by 1/sqrt(HC))
    proj3_kernel<<<dim3(NN / 32, 3), 256>>>(q_img, k_img, v_img,
                                            wq, bq, wk, bk, wv, bv);
    // 2: cluster sort (parallel scan)
    sortidx_kernel<<<1, 512>>>(labels);
    // 3: pc permute + kv gather + centers
    prep_kernel<<<NN + GATHER_BLOCKS + KK, 256>>>(pc, labels);
    // 4: split-K fused attention
    attn_kernel<<<dim3(NN / 32, NHEAD, 2), 256>>>(labels);
    // 5: rs1 = v + mlp1(attn)
    mlp_fused_kernel<<<NN / 32, 256>>>(w1a, b1a, w1b, b1b, gv, grs1, 0);
    // 6: out = rs1 + mlp2(rs1)
    mlp_fused_kernel<<<NN / 32, 256>>>(w2a, b2a, w2b, b2b, grs1, (float*)d_out, 1);
}

// round 12
// speedup vs baseline: 1.4154x; 1.1782x over previous
#include <cuda_runtime.h>

#define NN 2304          // H*W
#define CC 128           // channels
#define KK 16            // clusters
#define NHEAD 4
#define HCH 32           // head channels
#define C2 256           // 2*C
#define EPSV 1e-6f
#define INV_SCALE 0.17677669529663687f   // 1/sqrt(32)

// -------- scratch (device globals; no allocation allowed) --------
__device__ float g_q[NN * CC];       // scaled by 1/sqrt(HC)
__device__ float g_k[NN * CC];
__device__ float g_v[NN * CC];
__device__ float g_ksort[NN * CC];   // k rows permuted into cluster order
__device__ float g_vsort[NN * CC];
__device__ float g_pcs[NN * NN];     // pc columns permuted into cluster order
__device__ int   g_perm[NN];         // sorted pos -> original index
__device__ int   g_labsort[NN];      // label at sorted pos
__device__ int   g_coff[KK + 1];     // cluster offsets in sorted order
__device__ float g_cent[KK * CC];
__device__ float g_accp[2 * NN * CC];       // split-K partial weighted sums
__device__ float g_esump[2 * NN * NHEAD];   // split-K partial softmax denoms
__device__ float g_rs1[NN * CC];     // channel-major [C][N]

// ================= fused triple projection, 16-row tiles (blockIdx.y = q/k/v)
__global__ __launch_bounds__(256) void proj3_kernel(
    const float* __restrict__ qi, const float* __restrict__ ki, const float* __restrict__ vi,
    const float* __restrict__ wq, const float* __restrict__ bq,
    const float* __restrict__ wk, const float* __restrict__ bk,
    const float* __restrict__ wv, const float* __restrict__ bv) {
    int which = blockIdx.y;
    const float* img = which == 0 ? qi : which == 1 ? ki : vi;
    const float* w   = which == 0 ? wq : which == 1 ? wk : wv;
    const float* b   = which == 0 ? bq : which == 1 ? bk : bv;
    float* out       = which == 0 ? g_q : which == 1 ? g_k : g_v;
    float scale      = which == 0 ? INV_SCALE : 1.0f;

    __shared__ float xs[16 * 129];
    int n0 = blockIdx.x * 16;
    int tid = threadIdx.x;
    for (int idx = tid; idx < 16 * 128; idx += 256) {
        int nn = idx & 15, ci = idx >> 4;
        xs[nn * 129 + ci] = img[ci * NN + n0 + nn];
    }
    __syncthreads();
    int co = tid & 127, half = tid >> 7;
    float acc[8];
#pragma unroll
    for (int n = 0; n < 8; n++) acc[n] = 0.f;
    for (int ci = 0; ci < 128; ci++) {
        float wv2 = w[ci * 128 + co];
#pragma unroll
        for (int n = 0; n < 8; n++) acc[n] += xs[(half * 8 + n) * 129 + ci] * wv2;
    }
    float bv2 = b[co];
#pragma unroll
    for (int n = 0; n < 8; n++)
        out[(n0 + half * 8 + n) * CC + co] = (acc[n] + bv2) * scale;
}

// ================= stable counting sort, parallel warp-scan version (512 thr)
#define CHUNK 9   // 256*9 = 2304
__global__ __launch_bounds__(512) void sortidx_kernel(const int* __restrict__ labels) {
    __shared__ int labs[NN];
    __shared__ int cnt[256][KK + 1];
    __shared__ int tot[KK], coff[KK + 1];
    int tid = threadIdx.x;
    for (int i = tid; i < NN; i += 512) labs[i] = labels[i];
    if (tid < 256) {
#pragma unroll
        for (int k = 0; k < KK; k++) cnt[tid][k] = 0;
    }
    __syncthreads();
    if (tid < 256) {
        int base = tid * CHUNK;
#pragma unroll
        for (int c = 0; c < CHUNK; c++) cnt[tid][labs[base + c]]++;
    }
    __syncthreads();
    int warp = tid >> 5, lane = tid & 31;
    {   // warp k computes exclusive running offsets over the 256 thread-counts
        int k = warp;   // 16 warps == 16 clusters
        int run = 0;
#pragma unroll
        for (int g = 0; g < 8; g++) {
            int t = g * 32 + lane;
            int c = cnt[t][k];
            int x = c;
#pragma unroll
            for (int off = 1; off < 32; off <<= 1) {
                int y = __shfl_up_sync(0xffffffffu, x, off);
                if (lane >= off) x += y;
            }
            cnt[t][k] = run + (x - c);      // exclusive within-cluster offset
            run += __shfl_sync(0xffffffffu, x, 31);
        }
        if (lane == 0) tot[k] = run;
    }
    __syncthreads();
    if (tid == 0) {   // tiny 16-element scan
        int s = 0;
        for (int k = 0; k < KK; k++) { coff[k] = s; s += tot[k]; }
        coff[KK] = s;
        for (int k = 0; k <= KK; k++) g_coff[k] = coff[k];
    }
    __syncthreads();
    {   // add cluster base offsets
        int k = warp;
        int ck = coff[k];
#pragma unroll
        for (int g = 0; g < 8; g++) cnt[g * 32 + lane][k] += ck;
    }
    __syncthreads();
    if (tid < 256) {
        int base = tid * CHUNK;
#pragma unroll
        for (int c = 0; c < CHUNK; c++) {
            int n = base + c;
            int k = labs[n];
            int pos = cnt[tid][k]++;
            g_perm[pos] = n;
            g_labsort[pos] = k;
        }
    }
}

// ================= fused prep: pc column-permute + kv gather + centers
#define GATHER_BLOCKS (NN * 32 / 256)   // 288
__global__ __launch_bounds__(256) void prep_kernel(
    const float* __restrict__ pc, const int* __restrict__ labels) {
    __shared__ float row[NN];
    __shared__ float part[2][128];
    int bid = blockIdx.x, tid = threadIdx.x;

    if (bid < NN) {   // ---- permute one pc row's columns into sorted order
        const float* src = pc + (long)bid * NN;
        for (int j = tid; j < NN; j += 256) row[j] = src[j];
        __syncthreads();
        float* dst = g_pcs + (long)bid * NN;
        for (int p = tid; p < NN; p += 256) dst[p] = row[g_perm[p]];
    } else if (bid < NN + GATHER_BLOCKS) {   // ---- gather k,v rows
        int idx = (bid - NN) * 256 + tid;
        int pos = idx >> 5, f = idx & 31;
        int j = g_perm[pos];
        ((float4*)g_ksort)[pos * 32 + f] = ((const float4*)g_k)[j * 32 + f];
        ((float4*)g_vsort)[pos * 32 + f] = ((const float4*)g_v)[j * 32 + f];
    } else {   // ---- centers from UNSORTED k (independent of gather)
        int k = bid - NN - GATHER_BLOCKS;
        int g = tid >> 7, ch = tid & 127;
        int h0 = g * (NN / 2), h1 = h0 + NN / 2;
        float sum = 0.f;
        for (int n = h0; n < h1; n++)
            if (labels[n] == k) sum += g_k[n * CC + ch];
        part[g][ch] = sum;
        __syncthreads();
        if (g == 0) {
            int len = g_coff[k + 1] - g_coff[k];
            g_cent[k * CC + ch] = (part[0][ch] + part[1][ch]) / ((float)len + EPSV);
        }
    }
}

// ================= fused clustered attention, split-K=2 over sorted keys
// grid (NN/32, NHEAD, 2); 256 thr = 8 warps x 4 rows; fixed-max softmax.
// Register diet: no k-row preload (dot reads smem directly; rare after sort),
// min-3-blocks launch bound -> ~45% occupancy to hide LDS latency.
#define RW 4
#define PAD 36   // 9 float4s/row -> odd float4 stride -> conflict-free LDS.128
#define NT (NN / 32)   // 72 tiles
__global__ __launch_bounds__(256, 3) void attn_kernel(const int* __restrict__ labels) {
    __shared__ float qs[32 * PAD];
    __shared__ float cens[KK * PAD];
    __shared__ float cs[32][KK];
    __shared__ float ks[2][32 * PAD];    // [buf][j][d]
    __shared__ float vsT[2][32 * PAD];   // [buf][d][j]
    __shared__ float es[8][RW * 32];     // per-warp exp weights
    __shared__ int labt[2][32];

    int h = blockIdx.y;
    int z = blockIdx.z;
    int i0 = blockIdx.x * 32;
    int tid = threadIdx.x;
    int warp = tid >> 5, lane = tid & 31;
    int hoff = h * HCH;
    int t0 = z * (NT / 2), t1 = t0 + NT / 2;

    {   // q tile + centers
        int r = tid >> 3, d4 = (tid & 7) * 4;
        *(float4*)&qs[r * PAD + d4] = *(const float4*)&g_q[(i0 + r) * CC + hoff + d4];
        if (tid < KK * 8)
            *(float4*)&cens[r * PAD + d4] = *(const float4*)&g_cent[r * CC + hoff + d4];
    }
    __syncthreads();
#pragma unroll
    for (int p = 0; p < 2; p++) {   // cs[r][t] = q_r . center_t
        int task = tid + 256 * p;
        int r = task >> 4, t = task & 15;
        float s = 0.f;
#pragma unroll
        for (int d = 0; d < 32; d++) s += qs[r * PAD + d] * cens[t * PAD + d];
        cs[r][t] = s;
    }

    int mylab[RW];
    const float* pcrow[RW];
#pragma unroll
    for (int r = 0; r < RW; r++) {
        int i = i0 + warp * RW + r;
        mylab[r] = labels[i];
        pcrow[r] = g_pcs + (long)i * NN;
    }

    int tj = tid >> 3, td4 = (tid & 7) * 4;

    // ---- prologue: fetch tile t0 ----
    float4 kf = *(const float4*)&g_ksort[(t0 * 32 + tj) * CC + hoff + td4];
    float4 vf = *(const float4*)&g_vsort[(t0 * 32 + tj) * CC + hoff + td4];
    int lb = (tid < 32) ? g_labsort[t0 * 32 + tid] : 0;
    float pcn[RW];
#pragma unroll
    for (int r = 0; r < RW; r++) pcn[r] = pcrow[r][t0 * 32 + lane];

    {
        *(float4*)&ks[0][tj * PAD + td4] = kf;
        vsT[0][(td4 + 0) * PAD + tj] = vf.x;
        vsT[0][(td4 + 1) * PAD + tj] = vf.y;
        vsT[0][(td4 + 2) * PAD + tj] = vf.z;
        vsT[0][(td4 + 3) * PAD + tj] = vf.w;
        if (tid < 32) labt[0][tid] = lb;
    }

    float acc[RW], esum[RW];
#pragma unroll
    for (int r = 0; r < RW; r++) { acc[r] = 0.f; esum[r] = 0.f; }

    for (int t = t0; t < t1; t++) {
        int b = (t - t0) & 1;
        __syncthreads();

        float pccur[RW];
#pragma unroll
        for (int r = 0; r < RW; r++) pccur[r] = pcn[r];

        if (t + 1 < t1) {   // register prefetch of next tile
            int nbase = (t + 1) * 32;
            kf = *(const float4*)&g_ksort[(nbase + tj) * CC + hoff + td4];
            vf = *(const float4*)&g_vsort[(nbase + tj) * CC + hoff + td4];
            if (tid < 32) lb = g_labsort[nbase + tid];
#pragma unroll
            for (int r = 0; r < RW; r++) pcn[r] = pcrow[r][nbase + lane];
        }

        int lj = labt[b][lane];
#pragma unroll
        for (int r = 0; r < RW; r++) {
            unsigned m = __ballot_sync(0xffffffffu, lj == mylab[r]);
            float sc;
            if (m) {
                float dotv = 0.f;
                if (lj == mylab[r]) {
                    const float4* qp = (const float4*)&qs[(warp * RW + r) * PAD];
                    const float4* kp = (const float4*)&ks[b][lane * PAD];
#pragma unroll
                    for (int dd = 0; dd < 8; dd++) {
                        float4 a = qp[dd];   // broadcast
                        float4 bb = kp[dd];
                        dotv += a.x * bb.x + a.y * bb.y + a.z * bb.z + a.w * bb.w;
                    }
                }
                sc = (lj == mylab[r]) ? dotv : cs[warp * RW + r][lj] * pccur[r];
            } else {
                sc = cs[warp * RW + r][lj] * pccur[r];
            }
            float e = __expf(sc);   // bounded scores; fixed-max softmax
            es[warp][r * 32 + lane] = e;
            esum[r] += e;
        }
        __syncwarp();
        const float4* vr = (const float4*)&vsT[b][lane * PAD];
#pragma unroll
        for (int jj = 0; jj < 8; jj++) {
            float4 vv = vr[jj];
#pragma unroll
            for (int r = 0; r < RW; r++) {
                float4 ev = *(const float4*)&es[warp][r * 32 + jj * 4];   // broadcast
                acc[r] += ev.x * vv.x + ev.y * vv.y + ev.z * vv.z + ev.w * vv.w;
            }
        }
        __syncwarp();

        if (t + 1 < t1) {
            int nb = b ^ 1;
            *(float4*)&ks[nb][tj * PAD + td4] = kf;
            vsT[nb][(td4 + 0) * PAD + tj] = vf.x;
            vsT[nb][(td4 + 1) * PAD + tj] = vf.y;
            vsT[nb][(td4 + 2) * PAD + tj] = vf.z;
            vsT[nb][(td4 + 3) * PAD + tj] = vf.w;
            if (tid < 32) labt[nb][tid] = lb;
        }
    }
#pragma unroll
    for (int r = 0; r < RW; r++) {
        float S = esum[r];
#pragma unroll
        for (int o = 16; o; o >>= 1) S += __shfl_xor_sync(0xffffffffu, S, o);
        int i = i0 + warp * RW + r;
        g_accp[z * NN * CC + i * CC + hoff + lane] = acc[r];
        if (lane == 0) g_esump[z * NN * NHEAD + i * NHEAD + h] = S;
    }
}

// ================= fused MLP, 16-row tiles: stage A -> smem -> stage B + residual
// stage 0: x = combined attention out, base = v (n-major),   out = rs1 (chan-major)
// stage 1: x = rs1 (chan-major),       base = rs1 (chan-major), out = d_out
__global__ __launch_bounds__(256) void mlp_fused_kernel(
    const float* __restrict__ wa, const float* __restrict__ ba,
    const float* __restrict__ wb, const float* __restrict__ bb,
    const float* __restrict__ base, float* __restrict__ out, int stage) {
    __shared__ float xs[16 * 129];
    __shared__ float hs[16 * 257];
    int n0 = blockIdx.x * 16;
    int tid = threadIdx.x;

    if (stage == 0) {
        for (int idx = tid; idx < 16 * 128; idx += 256) {
            int ci = idx & 127, nn = idx >> 7;
            int i = n0 + nn, h = ci >> 5;
            float s = g_esump[i * NHEAD + h] + g_esump[NN * NHEAD + i * NHEAD + h];
            float a = g_accp[i * CC + ci] + g_accp[NN * CC + i * CC + ci];
            xs[nn * 129 + ci] = a / s;
        }
    } else {
        for (int idx = tid; idx < 16 * 128; idx += 256) {
            int nn = idx & 15, ci = idx >> 4;
            xs[nn * 129 + ci] = g_rs1[ci * NN + n0 + nn];
        }
    }
    __syncthreads();

    {   // stage A: hidden = leaky(x @ wa + ba), 256 hidden channels
        int co = tid;
        float acc[16];
#pragma unroll
        for (int n = 0; n < 16; n++) acc[n] = 0.f;
        for (int ci = 0; ci < 128; ci++) {
            float wv = wa[ci * C2 + co];
#pragma unroll
            for (int n = 0; n < 16; n++) acc[n] += xs[n * 129 + ci] * wv;
        }
        float bv = ba[co];
#pragma unroll
        for (int n = 0; n < 16; n++) {
            float y = acc[n] + bv;
            y = (y > 0.f) ? y : 0.01f * y;
            hs[n * 257 + co] = y;
        }
    }
    __syncthreads();

    {   // stage B: y = hidden @ wb + bb (+ residual), write chan-major
        int co = tid & 127, half = tid >> 7;
        float acc[8];
#pragma unroll
        for (int n = 0; n < 8; n++) acc[n] = 0.f;
        for (int ci = 0; ci < 256; ci++) {
            float wv = wb[ci * 128 + co];
#pragma unroll
            for (int n = 0; n < 8; n++) acc[n] += hs[(half * 8 + n) * 257 + ci] * wv;
        }
        float bv = bb[co];
        float* ys = xs;   // reuse (stage-A reads of xs are behind the barrier)
#pragma unroll
        for (int n = 0; n < 8; n++) {
            int nn = half * 8 + n;
            float y = acc[n] + bv;
            if (stage == 0) y += base[(n0 + nn) * CC + co];   // v, n-major
            ys[nn * 129 + co] = y;
        }
    }
    __syncthreads();
    for (int idx = tid; idx < 16 * 128; idx += 256) {
        int nn = idx & 15, c = idx >> 4;
        float y = xs[nn * 129 + c];
        if (stage == 1) y += base[c * NN + n0 + nn];   // rs1, chan-major
        out[c * NN + n0 + nn] = y;
    }
}

// ================= launch =================
extern "C" void kernel_launch(void* const* d_in, const int* in_sizes, int n_in,
                              void* d_out, int out_size) {
    const float* q_img = (const float*)d_in[0];
    const float* k_img = (const float*)d_in[1];
    const float* v_img = (const float*)d_in[2];
    const float* pc    = (const float*)d_in[3];

    // labels = unique input with exactly N=2304 elements
    int labIdx = -1;
    for (int i = 4; i < n_in; i++) if (in_sizes[i] == NN) { labIdx = i; break; }
    const int* labels = (const int*)d_in[labIdx];

    const float* wp[14]; int c = 0;
    for (int i = 4; i < n_in && c < 14; i++)
        if (i != labIdx) wp[c++] = (const float*)d_in[i];
    const float *wq = wp[0], *bq = wp[1], *wk = wp[2], *bk = wp[3];
    const float *wv = wp[4], *bv = wp[5];
    const float *w1a = wp[6], *b1a = wp[7], *w1b = wp[8], *b1b = wp[9];
    const float *w2a = wp[10], *b2a = wp[11], *w2b = wp[12], *b2b = wp[13];

    float *gv, *grs1;
    cudaGetSymbolAddress((void**)&gv, g_v);
    cudaGetSymbolAddress((void**)&grs1, g_rs1);

    // 1: all three projections (q pre-scaled by 1/sqrt(HC))
    proj3_kernel<<<dim3(NN / 16, 3), 256>>>(q_img, k_img, v_img,
                                            wq, bq, wk, bk, wv, bv);
    // 2: cluster sort (parallel scan)
    sortidx_kernel<<<1, 512>>>(labels);
    // 3: pc permute + kv gather + centers
    prep_kernel<<<NN + GATHER_BLOCKS + KK, 256>>>(pc, labels);
    // 4: split-K fused attention
    attn_kernel<<<dim3(NN / 32, NHEAD, 2), 256>>>(labels);
    // 5: rs1 = v + mlp1(attn)
    mlp_fused_kernel<<<NN / 16, 256>>>(w1a, b1a, w1b, b1b, gv, grs1, 0);
    // 6: out = rs1 + mlp2(rs1)
    mlp_fused_kernel<<<NN / 16, 256>>>(w2a, b2a, w2b, b2b, grs1, (float*)d_out, 1);
}